// round 10
// baseline (speedup 1.0000x reference)
#include <cuda_runtime.h>
#include <cuda_bf16.h>
#include <cstdint>

#define EPS 1e-5f
typedef unsigned long long u64;
typedef unsigned int u32;
typedef signed char s8;

// ---------------- device scratch ----------------
__device__ float g_a2[64], g_b2[64];
__device__ float g_a3[2048], g_b3[2048];
__device__ u64 g_w2bits[64 * 9];
__device__ u64 g_fc2bits[10 * 32];
__device__ u64 g_bits1[2048 * 14 * 14];
__device__ u64 g_bits2[2048 * 7 * 7];
__device__ u64 g_bits3[2048 * 32];
#define KPAD 3200
__device__ s8 g_afp8[2048 * KPAD];   // fc1 activations as s8 (+1/-1, 0 pad)
__device__ s8 g_wfp8[2048 * KPAD];   // fc1 weights as s8

// ---------------- packed f32x2 helpers ----------------
__device__ __forceinline__ u64 fma2(u64 a, u64 b, u64 c) {
    u64 d;
    asm("fma.rn.f32x2 %0, %1, %2, %3;" : "=l"(d) : "l"(a), "l"(b), "l"(c));
    return d;
}
__device__ __forceinline__ u64 pack2(float lo, float hi) {
    u64 d;
    asm("mov.b64 %0, {%1, %2};" : "=l"(d) : "f"(lo), "f"(hi));
    return d;
}
__device__ __forceinline__ void unpack2(u64 v, float& lo, float& hi) {
    asm("mov.b64 {%0, %1}, %2;" : "=f"(lo), "=f"(hi) : "l"(v));
}

// ================= kA: conv1 full + ALL weight prep (role by blockIdx) =================
#define NB_CONV1 1568
#define NB_FC1W  2048
#define NB_FC2W  10
#define NB_W2    64
#define NB_BN    8
#define NB_KA (NB_CONV1 + NB_FC1W + NB_FC2W + NB_W2 + NB_BN)

__global__ __launch_bounds__(256, 4) void kA(
    const float* __restrict__ x, const float* __restrict__ w1,
    const float* __restrict__ g1, const float* __restrict__ be1,
    const float* __restrict__ m1, const float* __restrict__ v1,
    const float* __restrict__ w2,
    const float* __restrict__ g2, const float* __restrict__ be2,
    const float* __restrict__ m2, const float* __restrict__ v2,
    const float* __restrict__ wfc1,
    const float* __restrict__ g3, const float* __restrict__ be3,
    const float* __restrict__ m3, const float* __restrict__ v3,
    const float* __restrict__ wfc2)
{
    __shared__ u64 sw[576];
    __shared__ float sa[64], sb[64];
    __shared__ u32 sbits[98];

    int bid = blockIdx.x;
    int tid = threadIdx.x;

    if (bid < NB_CONV1) {
        // ---- conv1 role (known-good) ----
        for (int i = tid; i < 576; i += 256) {
            float s = (w1[i] >= 0.0f) ? 1.0f : -1.0f;
            sw[i] = pack2(s, s);
        }
        if (tid < 64) {
            float a = g1[tid] / sqrtf(v1[tid] + EPS);
            sa[tid] = a;
            sb[tid] = be1[tid] - m1[tid] * a;
        }
        __syncthreads();

        int idx = bid * 256 + tid;
        int b = idx / 196, p = idx % 196;
        int py = p / 14, px = p % 14;
        const float* xb = x + b * 784;

        u64 pr[4][3];
#pragma unroll
        for (int r = 0; r < 4; r++) {
            int rr = 2 * py - 1 + r; rr = min(max(rr, 0), 27);
            const float* xr = xb + rr * 28;
            int c0 = max(2 * px - 1, 0);
            int c3 = min(2 * px + 2, 27);
            float f0 = xr[c0];
            float f1 = xr[2 * px];
            float f2 = xr[2 * px + 1];
            float f3 = xr[c3];
            pr[r][0] = pack2(f0, f1);
            pr[r][1] = pack2(f1, f2);
            pr[r][2] = pack2(f2, f3);
        }

        u64 word = 0ULL;
        for (int co = 0; co < 64; co += 2) {
            u64 a00 = 0ULL, a01 = 0ULL, a10 = 0ULL, a11 = 0ULL;
            const u64* w0 = &sw[co * 9];
#pragma unroll
            for (int ky = 0; ky < 3; ky++)
#pragma unroll
                for (int kx = 0; kx < 3; kx++) {
                    u64 wa = w0[ky * 3 + kx], wb = w0[9 + ky * 3 + kx];
                    a00 = fma2(wa, pr[ky][kx], a00);
                    a01 = fma2(wa, pr[ky + 1][kx], a01);
                    a10 = fma2(wb, pr[ky][kx], a10);
                    a11 = fma2(wb, pr[ky + 1][kx], a11);
                }
            float v0, v1x, v2, v3;
            unpack2(a00, v0, v1x); unpack2(a01, v2, v3);
            float m0 = fmaxf(fmaxf(v0, v1x), fmaxf(v2, v3));
            unpack2(a10, v0, v1x); unpack2(a11, v2, v3);
            float m1v = fmaxf(fmaxf(v0, v1x), fmaxf(v2, v3));
            if (fmaf(sa[co], m0, sb[co]) >= 0.0f)          word |= 1ULL << co;
            if (fmaf(sa[co + 1], m1v, sb[co + 1]) >= 0.0f) word |= 1ULL << (co + 1);
        }
        g_bits1[b * 196 + p] = word;

    } else if (bid < NB_CONV1 + NB_FC1W) {
        // ---- fc1 weight -> s8 expand role (one output row) ----
        int o = bid - NB_CONV1;
        const float* wo = wfc1 + (long long)o * 3136;
        u32* dst = (u32*)(g_wfp8 + (size_t)o * KPAD);
#pragma unroll
        for (int it = 0; it < 4; it++) {
            int q = it * 256 + tid;             // u32 index within row, need < 800
            if (q < 800) {
                u32 outw = 0;
#pragma unroll
                for (int i = 0; i < 4; i++) {
                    int kk = q * 4 + i;
                    u32 bval = 0;
                    if (kk < 3136) bval = (wo[kk] >= 0.0f) ? 0x01u : 0xFFu;
                    outw |= bval << (8 * i);
                }
                dst[q] = outw;
            }
        }

    } else if (bid < NB_CONV1 + NB_FC1W + NB_FC2W) {
        // ---- fc2 weight pack role ----
        int o = bid - NB_CONV1 - NB_FC1W;
        const float* wo = wfc2 + o * 2048;
#pragma unroll
        for (int it = 0; it < 8; it++) {
            int i = it * 256 + tid;
            u32 m = __ballot_sync(0xffffffffu, wo[i] >= 0.0f);
            if ((tid & 31) == 0) sbits[i >> 5] = m;
        }
        __syncthreads();
        if (tid < 32)
            g_fc2bits[o * 32 + tid] = (u64)sbits[2 * tid] | ((u64)sbits[2 * tid + 1] << 32);

    } else if (bid < NB_CONV1 + NB_FC1W + NB_FC2W + NB_W2) {
        // ---- conv2 weight pack role ----
        int co = bid - NB_CONV1 - NB_FC1W - NB_FC2W;
        const float* wc = w2 + co * 576;
#pragma unroll
        for (int it = 0; it < 3; it++) {
            int i = it * 256 + tid;
            bool v = (i < 576) ? (wc[i] >= 0.0f) : false;
            u32 m = __ballot_sync(0xffffffffu, v);
            if ((tid & 31) == 0 && i < 576) sbits[i >> 5] = m;
        }
        __syncthreads();
        if (tid < 9) {
            u64 word = 0ULL;
#pragma unroll
            for (int cin = 0; cin < 64; cin++) {
                int fi = cin * 9 + tid;
                word |= (u64)((sbits[fi >> 5] >> (fi & 31)) & 1u) << cin;
            }
            g_w2bits[co * 9 + tid] = word;
        }

    } else {
        // ---- bn fold role ----
        int i = (bid - NB_CONV1 - NB_FC1W - NB_FC2W - NB_W2) * 256 + tid;
        if (i < 2048) {
            float a = g3[i] / sqrtf(v3[i] + EPS);
            g_a3[i] = a;
            g_b3[i] = be3[i] - m3[i] * a;
        }
        if (i < 64) {
            float a = g2[i] / sqrtf(v2[i] + EPS);
            g_a2[i] = a;
            g_b2[i] = be2[i] - m2[i] * a;
        }
    }
}

// ================= conv2 + bn2 + sign + maxpool (known-good) =================
__global__ __launch_bounds__(128) void conv2_kernel() {
    __shared__ u64 sw[576];
    __shared__ float sa[64], sb[64];
    int tid = threadIdx.x;
    for (int i = tid; i < 576; i += 128) sw[i] = g_w2bits[i];
    if (tid < 64) { sa[tid] = g_a2[tid]; sb[tid] = g_b2[tid]; }
    __syncthreads();

    int idx = blockIdx.x * 128 + tid;
    if (idx >= 2048 * 49) return;
    int b = idx / 49, p = idx % 49;
    int py = p / 7, px = p % 7;
    const u64* ib = g_bits1 + b * 196;

    u64 pix[16];
#pragma unroll
    for (int i = 0; i < 4; i++) {
        int r = 2 * py - 1 + i; r = min(max(r, 0), 13);
#pragma unroll
        for (int j = 0; j < 4; j++) {
            int c = 2 * px - 1 + j; c = min(max(c, 0), 13);
            pix[i * 4 + j] = ib[r * 14 + c];
        }
    }

    u64 word = 0ULL;
    for (int co = 0; co < 64; co++) {
        u64 wreg[9];
#pragma unroll
        for (int t = 0; t < 9; t++) wreg[t] = sw[co * 9 + t];
        int smin = 1 << 30;
#pragma unroll
        for (int dy = 0; dy < 2; dy++)
#pragma unroll
            for (int dx = 0; dx < 2; dx++) {
                int s = 0;
#pragma unroll
                for (int ky = 0; ky < 3; ky++)
#pragma unroll
                    for (int kx = 0; kx < 3; kx++)
                        s += __popcll(pix[(dy + ky) * 4 + (dx + kx)] ^ wreg[ky * 3 + kx]);
                smin = min(smin, s);
            }
        float d = (float)(576 - 2 * smin);
        if (fmaf(sa[co], d, sb[co]) >= 0.0f) word |= 1ULL << co;
    }
    g_bits2[b * 49 + p] = word;
}

// ================= expand activations: g_bits2 -> s8 A [2048 x 3200] =================
__global__ void expand_a() {
    int idx = blockIdx.x * 256 + threadIdx.x;     // 2048*800
    int b = idx / 800, q = idx % 800;
    u32 outw = 0;
#pragma unroll
    for (int i = 0; i < 4; i++) {
        int kk = q * 4 + i;
        if (kk < 3136) {
            int c = kk / 49, j = kk - c * 49;
            u32 bit = (u32)(g_bits2[b * 49 + j] >> c) & 1u;
            outw |= (bit ? 0x01u : 0xFFu) << (8 * i);
        }
    }
    ((u32*)g_afp8)[idx] = outw;
}

// ================= fc1: int8 mma.sync GEMM + bn3 + sign + pack =================
// block tile: M=128 (8 warps x m16), N=64 (8 x n8 per warp), K chunks of 64.
// smem rows padded to 80 B -> conflict-free u32 fragment loads.
__global__ __launch_bounds__(256) void fc1_mma() {
    __shared__ __align__(16) s8 As[128 * 80];
    __shared__ __align__(16) s8 Bs[64 * 80];
    __shared__ u64 obits[128];
    __shared__ float sa3[64], sb3[64];
    int tid = threadIdx.x, w = tid >> 5, L = tid & 31;
    int m0 = blockIdx.y * 128, n0 = blockIdx.x * 64;

    if (tid < 64) { sa3[tid] = g_a3[n0 + tid]; sb3[tid] = g_b3[n0 + tid]; }
    if (tid < 128) obits[tid] = 0ULL;

    int acc[8][4];
#pragma unroll
    for (int j = 0; j < 8; j++)
#pragma unroll
        for (int i = 0; i < 4; i++) acc[j][i] = 0;

    const s8* gA = g_afp8 + (size_t)m0 * KPAD;
    const s8* gB = g_wfp8 + (size_t)n0 * KPAD;

    for (int kc = 0; kc < KPAD; kc += 64) {
        __syncthreads();
        // A chunk: 128 rows x 64 B = 512 uint4 (2 per thread)
#pragma unroll
        for (int t = 0; t < 2; t++) {
            int e = tid * 2 + t;
            int row = e >> 2, seg = e & 3;
            *(uint4*)(As + row * 80 + seg * 16) =
                *(const uint4*)(gA + (size_t)row * KPAD + kc + seg * 16);
        }
        // B chunk: 64 rows x 64 B = 256 uint4 (1 per thread)
        {
            int row = tid >> 2, seg = tid & 3;
            *(uint4*)(Bs + row * 80 + seg * 16) =
                *(const uint4*)(gB + (size_t)row * KPAD + kc + seg * 16);
        }
        __syncthreads();
#pragma unroll
        for (int ks = 0; ks < 2; ks++) {
            int kb = ks * 32 + (L & 3) * 4;
            const s8* ar = As + (w * 16 + (L >> 2)) * 80 + kb;
            u32 a0 = *(const u32*)ar;
            u32 a1 = *(const u32*)(ar + 8 * 80);
            u32 a2 = *(const u32*)(ar + 16);
            u32 a3 = *(const u32*)(ar + 8 * 80 + 16);
#pragma unroll
            for (int j = 0; j < 8; j++) {
                const s8* br = Bs + (j * 8 + (L >> 2)) * 80 + kb;
                u32 b0 = *(const u32*)br;
                u32 b1 = *(const u32*)(br + 16);
                asm volatile(
                    "mma.sync.aligned.m16n8k32.row.col.s32.s8.s8.s32 "
                    "{%0,%1,%2,%3}, {%4,%5,%6,%7}, {%8,%9}, {%0,%1,%2,%3};"
                    : "+r"(acc[j][0]), "+r"(acc[j][1]), "+r"(acc[j][2]), "+r"(acc[j][3])
                    : "r"(a0), "r"(a1), "r"(a2), "r"(a3), "r"(b0), "r"(b1));
            }
        }
    }

    // epilogue: exact s32 dot -> bn3 + sign + pack (local cols 0..63)
    u64 bitsA = 0ULL, bitsB = 0ULL;
#pragma unroll
    for (int j = 0; j < 8; j++) {
        int c0 = j * 8 + (L & 3) * 2, c1 = c0 + 1;
        if (fmaf(sa3[c0], (float)acc[j][0], sb3[c0]) >= 0.0f) bitsA |= 1ULL << c0;
        if (fmaf(sa3[c1], (float)acc[j][1], sb3[c1]) >= 0.0f) bitsA |= 1ULL << c1;
        if (fmaf(sa3[c0], (float)acc[j][2], sb3[c0]) >= 0.0f) bitsB |= 1ULL << c0;
        if (fmaf(sa3[c1], (float)acc[j][3], sb3[c1]) >= 0.0f) bitsB |= 1ULL << c1;
    }
    int lr = w * 16 + (L >> 2);
    atomicOr(&obits[lr], bitsA);
    atomicOr(&obits[lr + 8], bitsB);
    __syncthreads();
    if (tid < 128)
        g_bits3[(size_t)(m0 + tid) * 32 + blockIdx.x] = obits[tid];
}

// ================= fc2: warp-per-row XNOR + scale =================
__global__ __launch_bounds__(256) void fc2_kernel(float* __restrict__ out,
                                                  const float* __restrict__ scale) {
    __shared__ u64 sw[10][32];
    int tid = threadIdx.x;
    for (int i = tid; i < 320; i += 256)
        ((u64*)sw)[i] = g_fc2bits[i];
    __syncthreads();

    int warp = tid >> 5, lane = tid & 31;
    int b = blockIdx.x * 8 + warp;
    u64 xw = g_bits3[b * 32 + lane];
    float sc = scale[0];
#pragma unroll
    for (int o = 0; o < 10; o++) {
        u32 p = (u32)__popcll(xw ^ sw[o][lane]);
        u32 s = __reduce_add_sync(0xffffffffu, p);
        if (lane == o)
            out[b * 10 + o] = sc * (float)(2048 - 2 * (int)s);
    }
}

// ================= launch =================
extern "C" void kernel_launch(void* const* d_in, const int* in_sizes, int n_in,
                              void* d_out, int out_size) {
    const float* x       = (const float*)d_in[0];
    const float* conv1_w = (const float*)d_in[1];
    const float* bn1_g   = (const float*)d_in[2];
    const float* bn1_b   = (const float*)d_in[3];
    const float* bn1_m   = (const float*)d_in[4];
    const float* bn1_v   = (const float*)d_in[5];
    const float* conv2_w = (const float*)d_in[6];
    const float* bn2_g   = (const float*)d_in[7];
    const float* bn2_b   = (const float*)d_in[8];
    const float* bn2_m   = (const float*)d_in[9];
    const float* bn2_v   = (const float*)d_in[10];
    const float* fc1_w   = (const float*)d_in[11];
    const float* bn3_g   = (const float*)d_in[12];
    const float* bn3_b   = (const float*)d_in[13];
    const float* bn3_m   = (const float*)d_in[14];
    const float* bn3_v   = (const float*)d_in[15];
    const float* fc2_w   = (const float*)d_in[16];
    const float* scale   = (const float*)d_in[17];
    float* out = (float*)d_out;

    kA<<<NB_KA, 256>>>(x, conv1_w, bn1_g, bn1_b, bn1_m, bn1_v,
                       conv2_w, bn2_g, bn2_b, bn2_m, bn2_v,
                       fc1_w, bn3_g, bn3_b, bn3_m, bn3_v, fc2_w);
    conv2_kernel<<<784, 128>>>();
    expand_a<<<6400, 256>>>();
    fc1_mma<<<dim3(32, 16), 256>>>();
    fc2_kernel<<<256, 256>>>(out, scale);
}

// round 11
// speedup vs baseline: 1.2603x; 1.2603x over previous
#include <cuda_runtime.h>
#include <cuda_bf16.h>
#include <cstdint>

#define EPS 1e-5f
typedef unsigned long long u64;
typedef unsigned int u32;
typedef signed char s8;

// ---------------- device scratch ----------------
__device__ float g_a2[64], g_b2[64];
__device__ float g_a3[2048], g_b3[2048];
__device__ u64 g_w2bits[64 * 9];
__device__ u64 g_fc1bits[2048 * 49];     // bit-packed fc1 weights (rows < 1344)
__device__ u64 g_fc2bits[10 * 32];
__device__ u64 g_bits1[2048 * 14 * 14];
__device__ u64 g_bits2[2048 * 7 * 7];
__device__ u64 g_bits3[2048 * 32];
#define KPAD 3200
__device__ s8 g_afp8[2048 * KPAD];       // fc1 activations as s8 (full M)
__device__ s8 g_wfp8[2048 * KPAD];       // fc1 weights as s8 (rows >= 1344 valid)

#define NPOPC 21                          // n-tiles done by popcount; 32-NPOPC by IMMA
#define NSPLIT (NPOPC * 64)               // = 1344

// ---------------- packed f32x2 helpers ----------------
__device__ __forceinline__ u64 fma2(u64 a, u64 b, u64 c) {
    u64 d;
    asm("fma.rn.f32x2 %0, %1, %2, %3;" : "=l"(d) : "l"(a), "l"(b), "l"(c));
    return d;
}
__device__ __forceinline__ u64 pack2(float lo, float hi) {
    u64 d;
    asm("mov.b64 %0, {%1, %2};" : "=l"(d) : "f"(lo), "f"(hi));
    return d;
}
__device__ __forceinline__ void unpack2(u64 v, float& lo, float& hi) {
    asm("mov.b64 {%0, %1}, %2;" : "=f"(lo), "=f"(hi) : "l"(v));
}

// ================= kA: conv1 full + ALL weight prep (role by blockIdx) =================
#define NB_CONV1 1568
#define NB_FC1W  2048
#define NB_FC2W  10
#define NB_W2    64
#define NB_BN    8
#define NB_KA (NB_CONV1 + NB_FC1W + NB_FC2W + NB_W2 + NB_BN)

__global__ __launch_bounds__(256, 4) void kA(
    const float* __restrict__ x, const float* __restrict__ w1,
    const float* __restrict__ g1, const float* __restrict__ be1,
    const float* __restrict__ m1, const float* __restrict__ v1,
    const float* __restrict__ w2,
    const float* __restrict__ g2, const float* __restrict__ be2,
    const float* __restrict__ m2, const float* __restrict__ v2,
    const float* __restrict__ wfc1,
    const float* __restrict__ g3, const float* __restrict__ be3,
    const float* __restrict__ m3, const float* __restrict__ v3,
    const float* __restrict__ wfc2)
{
    __shared__ u64 sw[576];
    __shared__ float sa[64], sb[64];
    __shared__ u32 sbits[98];
    __shared__ u32 sp[98];

    int bid = blockIdx.x;
    int tid = threadIdx.x;

    if (bid < NB_CONV1) {
        // ---- conv1 role (known-good) ----
        for (int i = tid; i < 576; i += 256) {
            float s = (w1[i] >= 0.0f) ? 1.0f : -1.0f;
            sw[i] = pack2(s, s);
        }
        if (tid < 64) {
            float a = g1[tid] / sqrtf(v1[tid] + EPS);
            sa[tid] = a;
            sb[tid] = be1[tid] - m1[tid] * a;
        }
        __syncthreads();

        int idx = bid * 256 + tid;
        int b = idx / 196, p = idx % 196;
        int py = p / 14, px = p % 14;
        const float* xb = x + b * 784;

        u64 pr[4][3];
#pragma unroll
        for (int r = 0; r < 4; r++) {
            int rr = 2 * py - 1 + r; rr = min(max(rr, 0), 27);
            const float* xr = xb + rr * 28;
            int c0 = max(2 * px - 1, 0);
            int c3 = min(2 * px + 2, 27);
            float f0 = xr[c0];
            float f1 = xr[2 * px];
            float f2 = xr[2 * px + 1];
            float f3 = xr[c3];
            pr[r][0] = pack2(f0, f1);
            pr[r][1] = pack2(f1, f2);
            pr[r][2] = pack2(f2, f3);
        }

        u64 word = 0ULL;
        for (int co = 0; co < 64; co += 2) {
            u64 a00 = 0ULL, a01 = 0ULL, a10 = 0ULL, a11 = 0ULL;
            const u64* w0 = &sw[co * 9];
#pragma unroll
            for (int ky = 0; ky < 3; ky++)
#pragma unroll
                for (int kx = 0; kx < 3; kx++) {
                    u64 wa = w0[ky * 3 + kx], wb = w0[9 + ky * 3 + kx];
                    a00 = fma2(wa, pr[ky][kx], a00);
                    a01 = fma2(wa, pr[ky + 1][kx], a01);
                    a10 = fma2(wb, pr[ky][kx], a10);
                    a11 = fma2(wb, pr[ky + 1][kx], a11);
                }
            float v0, v1x, v2, v3;
            unpack2(a00, v0, v1x); unpack2(a01, v2, v3);
            float m0 = fmaxf(fmaxf(v0, v1x), fmaxf(v2, v3));
            unpack2(a10, v0, v1x); unpack2(a11, v2, v3);
            float m1v = fmaxf(fmaxf(v0, v1x), fmaxf(v2, v3));
            if (fmaf(sa[co], m0, sb[co]) >= 0.0f)          word |= 1ULL << co;
            if (fmaf(sa[co + 1], m1v, sb[co + 1]) >= 0.0f) word |= 1ULL << (co + 1);
        }
        g_bits1[b * 196 + p] = word;

    } else if (bid < NB_CONV1 + NB_FC1W) {
        // ---- fc1 weight role: rows < NSPLIT -> bit-pack; rows >= NSPLIT -> s8 expand ----
        int o = bid - NB_CONV1;
        const float* wo = wfc1 + (long long)o * 3136;
        if (o < NSPLIT) {
#pragma unroll
            for (int it = 0; it < 13; it++) {
                int i = it * 256 + tid;
                bool v = (i < 3136) ? (wo[i] >= 0.0f) : false;
                u32 m = __ballot_sync(0xffffffffu, v);
                if ((tid & 31) == 0 && i < 3136) sbits[i >> 5] = m;
            }
            __syncthreads();
            if (tid < 98) {
                int j = tid % 49, half = tid / 49;
                u32 part = 0;
#pragma unroll
                for (int cc = 0; cc < 32; cc++) {
                    int c = half * 32 + cc;
                    int fi = c * 49 + j;
                    part |= ((sbits[fi >> 5] >> (fi & 31)) & 1u) << cc;
                }
                sp[tid] = part;
            }
            __syncthreads();
            if (tid < 49)
                g_fc1bits[o * 49 + tid] = (u64)sp[tid] | ((u64)sp[tid + 49] << 32);
        } else {
            u32* dst = (u32*)(g_wfp8 + (size_t)o * KPAD);
#pragma unroll
            for (int it = 0; it < 4; it++) {
                int q = it * 256 + tid;
                if (q < 800) {
                    u32 outw = 0;
#pragma unroll
                    for (int i = 0; i < 4; i++) {
                        int kk = q * 4 + i;
                        u32 bval = 0;
                        if (kk < 3136) bval = (wo[kk] >= 0.0f) ? 0x01u : 0xFFu;
                        outw |= bval << (8 * i);
                    }
                    dst[q] = outw;
                }
            }
        }

    } else if (bid < NB_CONV1 + NB_FC1W + NB_FC2W) {
        // ---- fc2 weight pack role ----
        int o = bid - NB_CONV1 - NB_FC1W;
        const float* wo = wfc2 + o * 2048;
#pragma unroll
        for (int it = 0; it < 8; it++) {
            int i = it * 256 + tid;
            u32 m = __ballot_sync(0xffffffffu, wo[i] >= 0.0f);
            if ((tid & 31) == 0) sbits[i >> 5] = m;
        }
        __syncthreads();
        if (tid < 32)
            g_fc2bits[o * 32 + tid] = (u64)sbits[2 * tid] | ((u64)sbits[2 * tid + 1] << 32);

    } else if (bid < NB_CONV1 + NB_FC1W + NB_FC2W + NB_W2) {
        // ---- conv2 weight pack role ----
        int co = bid - NB_CONV1 - NB_FC1W - NB_FC2W;
        const float* wc = w2 + co * 576;
#pragma unroll
        for (int it = 0; it < 3; it++) {
            int i = it * 256 + tid;
            bool v = (i < 576) ? (wc[i] >= 0.0f) : false;
            u32 m = __ballot_sync(0xffffffffu, v);
            if ((tid & 31) == 0 && i < 576) sbits[i >> 5] = m;
        }
        __syncthreads();
        if (tid < 9) {
            u64 word = 0ULL;
#pragma unroll
            for (int cin = 0; cin < 64; cin++) {
                int fi = cin * 9 + tid;
                word |= (u64)((sbits[fi >> 5] >> (fi & 31)) & 1u) << cin;
            }
            g_w2bits[co * 9 + tid] = word;
        }

    } else {
        // ---- bn fold role ----
        int i = (bid - NB_CONV1 - NB_FC1W - NB_FC2W - NB_W2) * 256 + tid;
        if (i < 2048) {
            float a = g3[i] / sqrtf(v3[i] + EPS);
            g_a3[i] = a;
            g_b3[i] = be3[i] - m3[i] * a;
        }
        if (i < 64) {
            float a = g2[i] / sqrtf(v2[i] + EPS);
            g_a2[i] = a;
            g_b2[i] = be2[i] - m2[i] * a;
        }
    }
}

// ================= conv2 half-batch (known-good math) =================
__global__ __launch_bounds__(128) void conv2_kernel(int batch0) {
    __shared__ u64 sw[576];
    __shared__ float sa[64], sb[64];
    int tid = threadIdx.x;
    for (int i = tid; i < 576; i += 128) sw[i] = g_w2bits[i];
    if (tid < 64) { sa[tid] = g_a2[tid]; sb[tid] = g_b2[tid]; }
    __syncthreads();

    int idx = blockIdx.x * 128 + tid;       // [0, 1024*49)
    int b = batch0 + idx / 49, p = idx % 49;
    int py = p / 7, px = p % 7;
    const u64* ib = g_bits1 + b * 196;

    u64 pix[16];
#pragma unroll
    for (int i = 0; i < 4; i++) {
        int r = 2 * py - 1 + i; r = min(max(r, 0), 13);
#pragma unroll
        for (int j = 0; j < 4; j++) {
            int c = 2 * px - 1 + j; c = min(max(c, 0), 13);
            pix[i * 4 + j] = ib[r * 14 + c];
        }
    }

    u64 word = 0ULL;
    for (int co = 0; co < 64; co++) {
        u64 wreg[9];
#pragma unroll
        for (int t = 0; t < 9; t++) wreg[t] = sw[co * 9 + t];
        int smin = 1 << 30;
#pragma unroll
        for (int dy = 0; dy < 2; dy++)
#pragma unroll
            for (int dx = 0; dx < 2; dx++) {
                int s = 0;
#pragma unroll
                for (int ky = 0; ky < 3; ky++)
#pragma unroll
                    for (int kx = 0; kx < 3; kx++)
                        s += __popcll(pix[(dy + ky) * 4 + (dx + kx)] ^ wreg[ky * 3 + kx]);
                smin = min(smin, s);
            }
        float d = (float)(576 - 2 * smin);
        if (fmaf(sa[co], d, sb[co]) >= 0.0f) word |= 1ULL << co;
    }
    g_bits2[b * 49 + p] = word;
}

// ================= expand activations (half): g_bits2 -> s8 A =================
__global__ void expand_a(int base) {
    int idx = base + blockIdx.x * 256 + threadIdx.x;   // [0, 2048*800)
    int b = idx / 800, q = idx % 800;
    int kk0 = q * 4;
    int c = kk0 / 49;
    int j = kk0 - c * 49;
    u32 outw = 0;
#pragma unroll
    for (int i = 0; i < 4; i++) {
        int kk = kk0 + i;
        if (kk < 3136) {
            u32 bit = (u32)(g_bits2[b * 49 + j] >> c) & 1u;
            outw |= (bit ? 0x01u : 0xFFu) << (8 * i);
            if (++j == 49) { j = 0; ++c; }
        }
    }
    ((u32*)g_afp8)[idx] = outw;
}

// ================= fc1 hybrid: IMMA role (tensor pipe) + popc role (alu pipe) =================
// blocks [0, 176): mma   — 11 n-tiles x 16 m-tiles (cols [1344,2048), M tile 128)
// blocks [176, 848): popc — 21 n-tiles x 32 m-tiles (cols [0,1344), M tile 64)
#define NB_MMA ((32 - NPOPC) * 16)
#define NB_HYB (NB_MMA + NPOPC * 32)

__global__ __launch_bounds__(256) void fc1_hybrid() {
    __shared__ __align__(16) char buf[26624];
    int tid = threadIdx.x;
    int bid = blockIdx.x;

    if (bid < NB_MMA) {
        // ================== IMMA role (r10-proven fragment math) ==================
        s8* As = (s8*)buf;                       // 128*80
        s8* Bs = (s8*)(buf + 10240);             // 64*80
        u64* obits = (u64*)(buf + 15360);        // 128
        float* sa3 = (float*)(buf + 16384);
        float* sb3 = (float*)(buf + 16640);
        int w = tid >> 5, L = tid & 31;
        int nt = NPOPC + bid / 16;
        int m0 = (bid % 16) * 128, n0 = nt * 64;

        if (tid < 64) { sa3[tid] = g_a3[n0 + tid]; sb3[tid] = g_b3[n0 + tid]; }
        if (tid < 128) obits[tid] = 0ULL;

        int acc[8][4];
#pragma unroll
        for (int j = 0; j < 8; j++)
#pragma unroll
            for (int i = 0; i < 4; i++) acc[j][i] = 0;

        const s8* gA = g_afp8 + (size_t)m0 * KPAD;
        const s8* gB = g_wfp8 + (size_t)n0 * KPAD;

        for (int kc = 0; kc < KPAD; kc += 64) {
            __syncthreads();
#pragma unroll
            for (int t = 0; t < 2; t++) {
                int e = tid * 2 + t;
                int row = e >> 2, seg = e & 3;
                *(uint4*)(As + row * 80 + seg * 16) =
                    *(const uint4*)(gA + (size_t)row * KPAD + kc + seg * 16);
            }
            {
                int row = tid >> 2, seg = tid & 3;
                *(uint4*)(Bs + row * 80 + seg * 16) =
                    *(const uint4*)(gB + (size_t)row * KPAD + kc + seg * 16);
            }
            __syncthreads();
#pragma unroll
            for (int ks = 0; ks < 2; ks++) {
                int kb = ks * 32 + (L & 3) * 4;
                const s8* ar = As + (w * 16 + (L >> 2)) * 80 + kb;
                u32 a0 = *(const u32*)ar;
                u32 a1 = *(const u32*)(ar + 8 * 80);
                u32 a2 = *(const u32*)(ar + 16);
                u32 a3 = *(const u32*)(ar + 8 * 80 + 16);
#pragma unroll
                for (int j = 0; j < 8; j++) {
                    const s8* br = Bs + (j * 8 + (L >> 2)) * 80 + kb;
                    u32 b0 = *(const u32*)br;
                    u32 b1 = *(const u32*)(br + 16);
                    asm volatile(
                        "mma.sync.aligned.m16n8k32.row.col.s32.s8.s8.s32 "
                        "{%0,%1,%2,%3}, {%4,%5,%6,%7}, {%8,%9}, {%0,%1,%2,%3};"
                        : "+r"(acc[j][0]), "+r"(acc[j][1]), "+r"(acc[j][2]), "+r"(acc[j][3])
                        : "r"(a0), "r"(a1), "r"(a2), "r"(a3), "r"(b0), "r"(b1));
                }
            }
        }

        u64 bitsA = 0ULL, bitsB = 0ULL;
#pragma unroll
        for (int j = 0; j < 8; j++) {
            int c0 = j * 8 + (L & 3) * 2, c1 = c0 + 1;
            if (fmaf(sa3[c0], (float)acc[j][0], sb3[c0]) >= 0.0f) bitsA |= 1ULL << c0;
            if (fmaf(sa3[c1], (float)acc[j][1], sb3[c1]) >= 0.0f) bitsA |= 1ULL << c1;
            if (fmaf(sa3[c0], (float)acc[j][2], sb3[c0]) >= 0.0f) bitsB |= 1ULL << c0;
            if (fmaf(sa3[c1], (float)acc[j][3], sb3[c1]) >= 0.0f) bitsB |= 1ULL << c1;
        }
        int lr = w * 16 + (L >> 2);
        atomicOr(&obits[lr], bitsA);
        atomicOr(&obits[lr + 8], bitsB);
        __syncthreads();
        if (tid < 128)
            g_bits3[(size_t)(m0 + tid) * 32 + nt] = obits[tid];

    } else {
        // ================== popcount role (r9-proven math) ==================
        u64 (*sA)[25] = (u64(*)[25])buf;           // 64*25*8 = 12800
        u64 (*sB)[25] = (u64(*)[25])(buf + 12800);
        u64* obits = (u64*)(buf + 25600);          // 64
        float* sa3 = (float*)(buf + 26112);
        float* sb3 = (float*)(buf + 26368);
        int r0 = bid - NB_MMA;
        int nt = r0 / 32;
        int m0 = (r0 % 32) * 64, n0 = nt * 64;
        int tx = tid & 15, ty = tid >> 4;

        if (tid < 64) {
            obits[tid] = 0ULL;
            sa3[tid] = g_a3[n0 + tid];
            sb3[tid] = g_b3[n0 + tid];
        }

        int acc[4][4];
#pragma unroll
        for (int i = 0; i < 4; i++)
#pragma unroll
            for (int j = 0; j < 4; j++) acc[i][j] = 0;

        for (int e = tid; e < 64 * 25; e += 256) {
            int r = e / 25, kk = e % 25;
            sA[r][kk] = g_bits2[(m0 + r) * 49 + kk];
            sB[r][kk] = g_fc1bits[(n0 + r) * 49 + kk];
        }
        __syncthreads();
#pragma unroll 5
        for (int kk = 0; kk < 25; kk++) {
            u64 a0 = sA[ty][kk], a1 = sA[ty + 16][kk], a2 = sA[ty + 32][kk], a3 = sA[ty + 48][kk];
            u64 b0 = sB[tx][kk], b1 = sB[tx + 16][kk], b2 = sB[tx + 32][kk], b3 = sB[tx + 48][kk];
            acc[0][0] += __popcll(a0 ^ b0); acc[0][1] += __popcll(a0 ^ b1);
            acc[0][2] += __popcll(a0 ^ b2); acc[0][3] += __popcll(a0 ^ b3);
            acc[1][0] += __popcll(a1 ^ b0); acc[1][1] += __popcll(a1 ^ b1);
            acc[1][2] += __popcll(a1 ^ b2); acc[1][3] += __popcll(a1 ^ b3);
            acc[2][0] += __popcll(a2 ^ b0); acc[2][1] += __popcll(a2 ^ b1);
            acc[2][2] += __popcll(a2 ^ b2); acc[2][3] += __popcll(a2 ^ b3);
            acc[3][0] += __popcll(a3 ^ b0); acc[3][1] += __popcll(a3 ^ b1);
            acc[3][2] += __popcll(a3 ^ b2); acc[3][3] += __popcll(a3 ^ b3);
        }
        __syncthreads();
        for (int e = tid; e < 64 * 24; e += 256) {
            int r = e / 24, kk = e % 24;
            sA[r][kk] = g_bits2[(m0 + r) * 49 + 25 + kk];
            sB[r][kk] = g_fc1bits[(n0 + r) * 49 + 25 + kk];
        }
        __syncthreads();
#pragma unroll 4
        for (int kk = 0; kk < 24; kk++) {
            u64 a0 = sA[ty][kk], a1 = sA[ty + 16][kk], a2 = sA[ty + 32][kk], a3 = sA[ty + 48][kk];
            u64 b0 = sB[tx][kk], b1 = sB[tx + 16][kk], b2 = sB[tx + 32][kk], b3 = sB[tx + 48][kk];
            acc[0][0] += __popcll(a0 ^ b0); acc[0][1] += __popcll(a0 ^ b1);
            acc[0][2] += __popcll(a0 ^ b2); acc[0][3] += __popcll(a0 ^ b3);
            acc[1][0] += __popcll(a1 ^ b0); acc[1][1] += __popcll(a1 ^ b1);
            acc[1][2] += __popcll(a1 ^ b2); acc[1][3] += __popcll(a1 ^ b3);
            acc[2][0] += __popcll(a2 ^ b0); acc[2][1] += __popcll(a2 ^ b1);
            acc[2][2] += __popcll(a2 ^ b2); acc[2][3] += __popcll(a2 ^ b3);
            acc[3][0] += __popcll(a3 ^ b0); acc[3][1] += __popcll(a3 ^ b1);
            acc[3][2] += __popcll(a3 ^ b2); acc[3][3] += __popcll(a3 ^ b3);
        }

#pragma unroll
        for (int i = 0; i < 4; i++) {
            u64 bits = 0ULL;
#pragma unroll
            for (int j = 0; j < 4; j++) {
                int c = tx + 16 * j;
                float d = (float)(3136 - 2 * acc[i][j]);
                if (fmaf(sa3[c], d, sb3[c]) >= 0.0f) bits |= 1ULL << c;
            }
            atomicOr(&obits[ty + 16 * i], bits);
        }
        __syncthreads();
        if (tid < 64)
            g_bits3[(size_t)(m0 + tid) * 32 + nt] = obits[tid];
    }
}

// ================= fc2: warp-per-row XNOR + scale =================
__global__ __launch_bounds__(256) void fc2_kernel(float* __restrict__ out,
                                                  const float* __restrict__ scale) {
    __shared__ u64 sw[10][32];
    int tid = threadIdx.x;
    for (int i = tid; i < 320; i += 256)
        ((u64*)sw)[i] = g_fc2bits[i];
    __syncthreads();

    int warp = tid >> 5, lane = tid & 31;
    int b = blockIdx.x * 8 + warp;
    u64 xw = g_bits3[b * 32 + lane];
    float sc = scale[0];
#pragma unroll
    for (int o = 0; o < 10; o++) {
        u32 p = (u32)__popcll(xw ^ sw[o][lane]);
        u32 s = __reduce_add_sync(0xffffffffu, p);
        if (lane == o)
            out[b * 10 + o] = sc * (float)(2048 - 2 * (int)s);
    }
}

// ================= launch =================
extern "C" void kernel_launch(void* const* d_in, const int* in_sizes, int n_in,
                              void* d_out, int out_size) {
    const float* x       = (const float*)d_in[0];
    const float* conv1_w = (const float*)d_in[1];
    const float* bn1_g   = (const float*)d_in[2];
    const float* bn1_b   = (const float*)d_in[3];
    const float* bn1_m   = (const float*)d_in[4];
    const float* bn1_v   = (const float*)d_in[5];
    const float* conv2_w = (const float*)d_in[6];
    const float* bn2_g   = (const float*)d_in[7];
    const float* bn2_b   = (const float*)d_in[8];
    const float* bn2_m   = (const float*)d_in[9];
    const float* bn2_v   = (const float*)d_in[10];
    const float* fc1_w   = (const float*)d_in[11];
    const float* bn3_g   = (const float*)d_in[12];
    const float* bn3_b   = (const float*)d_in[13];
    const float* bn3_m   = (const float*)d_in[14];
    const float* bn3_v   = (const float*)d_in[15];
    const float* fc2_w   = (const float*)d_in[16];
    const float* scale   = (const float*)d_in[17];
    float* out = (float*)d_out;

    // 7 launches/iter so ncu slot #6 = fc1_hybrid
    kA<<<NB_KA, 256>>>(x, conv1_w, bn1_g, bn1_b, bn1_m, bn1_v,
                       conv2_w, bn2_g, bn2_b, bn2_m, bn2_v,
                       fc1_w, bn3_g, bn3_b, bn3_m, bn3_v, fc2_w);
    conv2_kernel<<<392, 128>>>(0);
    conv2_kernel<<<392, 128>>>(1024);
    expand_a<<<3200, 256>>>(0);
    expand_a<<<3200, 256>>>(3200 * 256);
    fc1_hybrid<<<NB_HYB, 256>>>();
    fc2_kernel<<<256, 256>>>(out, scale);
}

// round 12
// speedup vs baseline: 1.5442x; 1.2253x over previous
#include <cuda_runtime.h>
#include <cuda_bf16.h>
#include <cstdint>

#define EPS 1e-5f
typedef unsigned long long u64;
typedef unsigned int u32;
typedef unsigned short u16;

// ---------------- device scratch ----------------
__device__ float g_a2[64], g_b2[64];
__device__ float g_a3[2048], g_b3[2048];
__device__ u64 g_w2bits[64 * 9];
__device__ u64 g_fc1bits[2048 * 49];
__device__ u64 g_fc2bits[10 * 32];
__device__ u64 g_bits1[2048 * 14 * 14];
__device__ u64 g_bits2[2048 * 7 * 7];
__device__ u64 g_bits3[2048 * 32];

// ---------------- packed f32x2 helpers ----------------
__device__ __forceinline__ u64 fma2(u64 a, u64 b, u64 c) {
    u64 d;
    asm("fma.rn.f32x2 %0, %1, %2, %3;" : "=l"(d) : "l"(a), "l"(b), "l"(c));
    return d;
}
__device__ __forceinline__ u64 pack2(float lo, float hi) {
    u64 d;
    asm("mov.b64 %0, {%1, %2};" : "=l"(d) : "f"(lo), "f"(hi));
    return d;
}
__device__ __forceinline__ void unpack2(u64 v, float& lo, float& hi) {
    asm("mov.b64 {%0, %1}, %2;" : "=f"(lo), "=f"(hi) : "l"(v));
}

// ================= kA: conv1 full + heavy weight prep (role by blockIdx) =================
#define NB_CONV1 1568
#define NB_FC1W  2048
#define NB_W2    64
#define NB_KA (NB_CONV1 + NB_FC1W + NB_W2)

__global__ __launch_bounds__(256, 4) void kA(
    const float* __restrict__ x, const float* __restrict__ w1,
    const float* __restrict__ g1, const float* __restrict__ be1,
    const float* __restrict__ m1, const float* __restrict__ v1,
    const float* __restrict__ w2,
    const float* __restrict__ wfc1)
{
    __shared__ u64 sw[576];
    __shared__ float sa[64], sb[64];
    __shared__ u32 sbits[98];
    __shared__ u32 sp[98];

    int bid = blockIdx.x;
    int tid = threadIdx.x;

    if (bid < NB_CONV1) {
        // ---- conv1 role (known-good) ----
        for (int i = tid; i < 576; i += 256) {
            float s = (w1[i] >= 0.0f) ? 1.0f : -1.0f;
            sw[i] = pack2(s, s);
        }
        if (tid < 64) {
            float a = g1[tid] / sqrtf(v1[tid] + EPS);
            sa[tid] = a;
            sb[tid] = be1[tid] - m1[tid] * a;
        }
        __syncthreads();

        int idx = bid * 256 + tid;
        int b = idx / 196, p = idx % 196;
        int py = p / 14, px = p % 14;
        const float* xb = x + b * 784;

        u64 pr[4][3];
#pragma unroll
        for (int r = 0; r < 4; r++) {
            int rr = 2 * py - 1 + r; rr = min(max(rr, 0), 27);
            const float* xr = xb + rr * 28;
            int c0 = max(2 * px - 1, 0);
            int c3 = min(2 * px + 2, 27);
            float f0 = xr[c0];
            float f1 = xr[2 * px];
            float f2 = xr[2 * px + 1];
            float f3 = xr[c3];
            pr[r][0] = pack2(f0, f1);
            pr[r][1] = pack2(f1, f2);
            pr[r][2] = pack2(f2, f3);
        }

        u64 word = 0ULL;
        for (int co = 0; co < 64; co += 2) {
            u64 a00 = 0ULL, a01 = 0ULL, a10 = 0ULL, a11 = 0ULL;
            const u64* w0 = &sw[co * 9];
#pragma unroll
            for (int ky = 0; ky < 3; ky++)
#pragma unroll
                for (int kx = 0; kx < 3; kx++) {
                    u64 wa = w0[ky * 3 + kx], wb = w0[9 + ky * 3 + kx];
                    a00 = fma2(wa, pr[ky][kx], a00);
                    a01 = fma2(wa, pr[ky + 1][kx], a01);
                    a10 = fma2(wb, pr[ky][kx], a10);
                    a11 = fma2(wb, pr[ky + 1][kx], a11);
                }
            float v0, v1x, v2, v3;
            unpack2(a00, v0, v1x); unpack2(a01, v2, v3);
            float m0 = fmaxf(fmaxf(v0, v1x), fmaxf(v2, v3));
            unpack2(a10, v0, v1x); unpack2(a11, v2, v3);
            float m1v = fmaxf(fmaxf(v0, v1x), fmaxf(v2, v3));
            if (fmaf(sa[co], m0, sb[co]) >= 0.0f)          word |= 1ULL << co;
            if (fmaf(sa[co + 1], m1v, sb[co + 1]) >= 0.0f) word |= 1ULL << (co + 1);
        }
        g_bits1[b * 196 + p] = word;

    } else if (bid < NB_CONV1 + NB_FC1W) {
        // ---- fc1 weight pack role ----
        int o = bid - NB_CONV1;
        const float* wo = wfc1 + (long long)o * 3136;
#pragma unroll
        for (int it = 0; it < 13; it++) {
            int i = it * 256 + tid;
            bool v = (i < 3136) ? (wo[i] >= 0.0f) : false;
            u32 m = __ballot_sync(0xffffffffu, v);
            if ((tid & 31) == 0 && i < 3136) sbits[i >> 5] = m;
        }
        __syncthreads();
        if (tid < 98) {
            int j = tid % 49, half = tid / 49;
            u32 part = 0;
#pragma unroll
            for (int cc = 0; cc < 32; cc++) {
                int c = half * 32 + cc;
                int fi = c * 49 + j;
                part |= ((sbits[fi >> 5] >> (fi & 31)) & 1u) << cc;
            }
            sp[tid] = part;
        }
        __syncthreads();
        if (tid < 49)
            g_fc1bits[o * 49 + tid] = (u64)sp[tid] | ((u64)sp[tid + 49] << 32);

    } else {
        // ---- conv2 weight pack role ----
        int co = bid - NB_CONV1 - NB_FC1W;
        const float* wc = w2 + co * 576;
#pragma unroll
        for (int it = 0; it < 3; it++) {
            int i = it * 256 + tid;
            bool v = (i < 576) ? (wc[i] >= 0.0f) : false;
            u32 m = __ballot_sync(0xffffffffu, v);
            if ((tid & 31) == 0 && i < 576) sbits[i >> 5] = m;
        }
        __syncthreads();
        if (tid < 9) {
            u64 word = 0ULL;
#pragma unroll
            for (int cin = 0; cin < 64; cin++) {
                int fi = cin * 9 + tid;
                word |= (u64)((sbits[fi >> 5] >> (fi & 31)) & 1u) << cin;
            }
            g_w2bits[co * 9 + tid] = word;
        }
    }
}

// ================= tiny #2: bn folds =================
__global__ void k_bn(const float* __restrict__ g2, const float* __restrict__ be2,
                     const float* __restrict__ m2, const float* __restrict__ v2,
                     const float* __restrict__ g3, const float* __restrict__ be3,
                     const float* __restrict__ m3, const float* __restrict__ v3) {
    int i = blockIdx.x * 256 + threadIdx.x;
    if (i < 2048) {
        float a = g3[i] / sqrtf(v3[i] + EPS);
        g_a3[i] = a;
        g_b3[i] = be3[i] - m3[i] * a;
    }
    if (i < 64) {
        float a = g2[i] / sqrtf(v2[i] + EPS);
        g_a2[i] = a;
        g_b2[i] = be2[i] - m2[i] * a;
    }
}

// ================= tiny #3: fc2 weight pack =================
__global__ void k_fc2w(const float* __restrict__ wfc2) {
    __shared__ u32 sbits[64];
    int o = blockIdx.x;
    int tid = threadIdx.x;
    const float* wo = wfc2 + o * 2048;
#pragma unroll
    for (int it = 0; it < 8; it++) {
        int i = it * 256 + tid;
        u32 m = __ballot_sync(0xffffffffu, wo[i] >= 0.0f);
        if ((tid & 31) == 0) sbits[i >> 5] = m;
    }
    __syncthreads();
    if (tid < 32)
        g_fc2bits[o * 32 + tid] = (u64)sbits[2 * tid] | ((u64)sbits[2 * tid + 1] << 32);
}

// ================= conv2: 4-way channel-split (thread = pixel x co-group) =================
// idx = pixel*4 + cg; cg owns output channels [cg*16, cg*16+16).
// u16 planes alias the u64 channel word exactly (little endian): no atomics.
__global__ __launch_bounds__(256) void conv2_kernel() {
    __shared__ u64 sw[576];
    __shared__ float sa[64], sb[64];
    int tid = threadIdx.x;
    for (int i = tid; i < 576; i += 256) sw[i] = g_w2bits[i];
    if (tid < 64) { sa[tid] = g_a2[tid]; sb[tid] = g_b2[tid]; }
    __syncthreads();

    int idx = blockIdx.x * 256 + tid;       // [0, 2048*49*4)
    int cg = idx & 3;
    int pp = idx >> 2;
    int b = pp / 49, p = pp % 49;
    int py = p / 7, px = p % 7;
    const u64* ib = g_bits1 + b * 196;

    u64 pix[16];
#pragma unroll
    for (int i = 0; i < 4; i++) {
        int r = 2 * py - 1 + i; r = min(max(r, 0), 13);
#pragma unroll
        for (int j = 0; j < 4; j++) {
            int c = 2 * px - 1 + j; c = min(max(c, 0), 13);
            pix[i * 4 + j] = ib[r * 14 + c];
        }
    }

    u32 bits16 = 0;
    int co0 = cg * 16;
    for (int t = 0; t < 16; t++) {
        int co = co0 + t;
        u64 wreg[9];
#pragma unroll
        for (int q = 0; q < 9; q++) wreg[q] = sw[co * 9 + q];
        int smin = 1 << 30;
#pragma unroll
        for (int dy = 0; dy < 2; dy++)
#pragma unroll
            for (int dx = 0; dx < 2; dx++) {
                int s = 0;
#pragma unroll
                for (int ky = 0; ky < 3; ky++)
#pragma unroll
                    for (int kx = 0; kx < 3; kx++)
                        s += __popcll(pix[(dy + ky) * 4 + (dx + kx)] ^ wreg[ky * 3 + kx]);
                smin = min(smin, s);
            }
        float d = (float)(576 - 2 * smin);
        if (fmaf(sa[co], d, sb[co]) >= 0.0f) bits16 |= 1u << t;
    }
    ((u16*)g_bits2)[pp * 4 + cg] = (u16)bits16;
}

// ================= fc1: 64x64 XNOR GEMM + bn3 + sign + pack (r9 known-good) =================
__global__ __launch_bounds__(256) void fc1_kernel() {
    __shared__ u64 sA[64][25];
    __shared__ u64 sB[64][25];
    __shared__ u64 obits[64];
    __shared__ float sa3[64], sb3[64];
    int tid = threadIdx.x;
    int tx = tid & 15, ty = tid >> 4;
    int m0 = blockIdx.y * 64;
    int n0 = blockIdx.x * 64;

    if (tid < 64) {
        obits[tid] = 0ULL;
        sa3[tid] = g_a3[n0 + tid];
        sb3[tid] = g_b3[n0 + tid];
    }

    int acc[4][4];
#pragma unroll
    for (int i = 0; i < 4; i++)
#pragma unroll
        for (int j = 0; j < 4; j++) acc[i][j] = 0;

    for (int e = tid; e < 64 * 25; e += 256) {
        int r = e / 25, kk = e % 25;
        sA[r][kk] = g_bits2[(m0 + r) * 49 + kk];
        sB[r][kk] = g_fc1bits[(n0 + r) * 49 + kk];
    }
    __syncthreads();
#pragma unroll 5
    for (int kk = 0; kk < 25; kk++) {
        u64 a0 = sA[ty][kk], a1 = sA[ty + 16][kk], a2 = sA[ty + 32][kk], a3 = sA[ty + 48][kk];
        u64 b0 = sB[tx][kk], b1 = sB[tx + 16][kk], b2 = sB[tx + 32][kk], b3 = sB[tx + 48][kk];
        acc[0][0] += __popcll(a0 ^ b0); acc[0][1] += __popcll(a0 ^ b1);
        acc[0][2] += __popcll(a0 ^ b2); acc[0][3] += __popcll(a0 ^ b3);
        acc[1][0] += __popcll(a1 ^ b0); acc[1][1] += __popcll(a1 ^ b1);
        acc[1][2] += __popcll(a1 ^ b2); acc[1][3] += __popcll(a1 ^ b3);
        acc[2][0] += __popcll(a2 ^ b0); acc[2][1] += __popcll(a2 ^ b1);
        acc[2][2] += __popcll(a2 ^ b2); acc[2][3] += __popcll(a2 ^ b3);
        acc[3][0] += __popcll(a3 ^ b0); acc[3][1] += __popcll(a3 ^ b1);
        acc[3][2] += __popcll(a3 ^ b2); acc[3][3] += __popcll(a3 ^ b3);
    }
    __syncthreads();
    for (int e = tid; e < 64 * 24; e += 256) {
        int r = e / 24, kk = e % 24;
        sA[r][kk] = g_bits2[(m0 + r) * 49 + 25 + kk];
        sB[r][kk] = g_fc1bits[(n0 + r) * 49 + 25 + kk];
    }
    __syncthreads();
#pragma unroll 4
    for (int kk = 0; kk < 24; kk++) {
        u64 a0 = sA[ty][kk], a1 = sA[ty + 16][kk], a2 = sA[ty + 32][kk], a3 = sA[ty + 48][kk];
        u64 b0 = sB[tx][kk], b1 = sB[tx + 16][kk], b2 = sB[tx + 32][kk], b3 = sB[tx + 48][kk];
        acc[0][0] += __popcll(a0 ^ b0); acc[0][1] += __popcll(a0 ^ b1);
        acc[0][2] += __popcll(a0 ^ b2); acc[0][3] += __popcll(a0 ^ b3);
        acc[1][0] += __popcll(a1 ^ b0); acc[1][1] += __popcll(a1 ^ b1);
        acc[1][2] += __popcll(a1 ^ b2); acc[1][3] += __popcll(a1 ^ b3);
        acc[2][0] += __popcll(a2 ^ b0); acc[2][1] += __popcll(a2 ^ b1);
        acc[2][2] += __popcll(a2 ^ b2); acc[2][3] += __popcll(a2 ^ b3);
        acc[3][0] += __popcll(a3 ^ b0); acc[3][1] += __popcll(a3 ^ b1);
        acc[3][2] += __popcll(a3 ^ b2); acc[3][3] += __popcll(a3 ^ b3);
    }

#pragma unroll
    for (int i = 0; i < 4; i++) {
        u64 bits = 0ULL;
#pragma unroll
        for (int j = 0; j < 4; j++) {
            int c = tx + 16 * j;
            float d = (float)(3136 - 2 * acc[i][j]);
            if (fmaf(sa3[c], d, sb3[c]) >= 0.0f) bits |= 1ULL << c;
        }
        atomicOr(&obits[ty + 16 * i], bits);
    }
    __syncthreads();
    if (tid < 64)
        g_bits3[(m0 + tid) * 32 + blockIdx.x] = obits[tid];
}

// ================= fc2: warp-per-row XNOR + scale (r9 known-good) =================
__global__ __launch_bounds__(256) void fc2_kernel(float* __restrict__ out,
                                                  const float* __restrict__ scale) {
    __shared__ u64 sw[10][32];
    int tid = threadIdx.x;
    for (int i = tid; i < 320; i += 256)
        ((u64*)sw)[i] = g_fc2bits[i];
    __syncthreads();

    int warp = tid >> 5, lane = tid & 31;
    int b = blockIdx.x * 8 + warp;
    u64 xw = g_bits3[b * 32 + lane];
    float sc = scale[0];
#pragma unroll
    for (int o = 0; o < 10; o++) {
        u32 p = (u32)__popcll(xw ^ sw[o][lane]);
        u32 s = __reduce_add_sync(0xffffffffu, p);
        if (lane == o)
            out[b * 10 + o] = sc * (float)(2048 - 2 * (int)s);
    }
}

// ================= launch =================
extern "C" void kernel_launch(void* const* d_in, const int* in_sizes, int n_in,
                              void* d_out, int out_size) {
    const float* x       = (const float*)d_in[0];
    const float* conv1_w = (const float*)d_in[1];
    const float* bn1_g   = (const float*)d_in[2];
    const float* bn1_b   = (const float*)d_in[3];
    const float* bn1_m   = (const float*)d_in[4];
    const float* bn1_v   = (const float*)d_in[5];
    const float* conv2_w = (const float*)d_in[6];
    const float* bn2_g   = (const float*)d_in[7];
    const float* bn2_b   = (const float*)d_in[8];
    const float* bn2_m   = (const float*)d_in[9];
    const float* bn2_v   = (const float*)d_in[10];
    const float* fc1_w   = (const float*)d_in[11];
    const float* bn3_g   = (const float*)d_in[12];
    const float* bn3_b   = (const float*)d_in[13];
    const float* bn3_m   = (const float*)d_in[14];
    const float* bn3_v   = (const float*)d_in[15];
    const float* fc2_w   = (const float*)d_in[16];
    const float* scale   = (const float*)d_in[17];
    float* out = (float*)d_out;

    // launch order: conv2 is #4 (profiler slot)
    kA<<<NB_KA, 256>>>(x, conv1_w, bn1_g, bn1_b, bn1_m, bn1_v, conv2_w, fc1_w);
    k_bn<<<8, 256>>>(bn2_g, bn2_b, bn2_m, bn2_v, bn3_g, bn3_b, bn3_m, bn3_v);
    k_fc2w<<<10, 256>>>(fc2_w);
    conv2_kernel<<<1568, 256>>>();          // 2048*49*4 threads
    fc1_kernel<<<dim3(32, 32), 256>>>();
    fc2_kernel<<<256, 256>>>(out, scale);
}